// round 1
// baseline (speedup 1.0000x reference)
#include <cuda_runtime.h>
#include <math.h>

// Block_36455682408804: transformer block
// B=16, T=1024, D=128, H=8, HS=16, FF=512
// inputs: x, Wq,bq, Wk,bk, Wv,bv, Wp,bp, W1,b1, W2,b2, g1,be1, g2,be2

#define BT_TOTAL 16384
#define DMODEL   128
#define FFDIM    512
#define NQKV     384

// scratch (device globals: allocation-free, graph-capturable)
__device__ float g_wqkv[DMODEL * NQKV];
__device__ float g_bqkv[NQKV];
__device__ float g_qkv[BT_TOTAL * NQKV];     // rows (b*1024+t): [0:128)=q, [128:256)=k, [256:384)=v  (col = h*16+s)
__device__ float g_att[BT_TOTAL * DMODEL];   // concat-head attention output
__device__ float g_x1 [BT_TOTAL * DMODEL];   // after LN1
__device__ float g_hid[BT_TOTAL * FFDIM];    // gelu(x1@W1+b1)

// ---------------------------------------------------------------------------
// Pack per-head QKV weights [H,D,HS] into one [D, 384] matrix (+ packed bias)
// ---------------------------------------------------------------------------
__global__ void pack_w_kernel(const float* __restrict__ Wq, const float* __restrict__ bq,
                              const float* __restrict__ Wk, const float* __restrict__ bk,
                              const float* __restrict__ Wv, const float* __restrict__ bv)
{
    int i = blockIdx.x * blockDim.x + threadIdx.x;
    if (i < DMODEL * NQKV) {
        int d = i / NQKV, n = i % NQKV;
        float v;
        if (n < 128)       { v = Wq[((n >> 4) << 11) + d * 16 + (n & 15)]; }
        else if (n < 256)  { int nn = n - 128; v = Wk[((nn >> 4) << 11) + d * 16 + (nn & 15)]; }
        else               { int nn = n - 256; v = Wv[((nn >> 4) << 11) + d * 16 + (nn & 15)]; }
        g_wqkv[i] = v;
    }
    if (i < NQKV) {
        g_bqkv[i] = (i < 128) ? bq[i] : (i < 256 ? bk[i - 128] : bv[i - 256]);
    }
}

// ---------------------------------------------------------------------------
// Generic K=128 sgemm: C[M,N] = A[M,128] @ B[128,N] + bias (optional exact GELU)
// BM=BN=64, BK=64 (2 chunks), 256 threads, 4x4 microtile
// ---------------------------------------------------------------------------
__global__ void gemm_k128(const float* __restrict__ A, const float* __restrict__ B,
                          const float* __restrict__ bias, float* __restrict__ C,
                          int N, int dogelu)
{
    __shared__ float As[64][68];   // padded: conflict-free broadcast reads
    __shared__ float Bs[64][64];
    const int m0 = blockIdx.x * 64;
    const int n0 = blockIdx.y * 64;
    const int tid = threadIdx.x;
    const int tx = tid & 15, ty = tid >> 4;
    float acc[4][4] = {};
    for (int kc = 0; kc < 128; kc += 64) {
        {
            int k4 = tid & 15, r0 = tid >> 4;
            #pragma unroll
            for (int rr = 0; rr < 4; ++rr) {
                int r = r0 + rr * 16;
                float4 v = *(const float4*)(A + (size_t)(m0 + r) * 128 + kc + k4 * 4);
                As[r][k4*4+0] = v.x; As[r][k4*4+1] = v.y;
                As[r][k4*4+2] = v.z; As[r][k4*4+3] = v.w;
            }
            #pragma unroll
            for (int rr = 0; rr < 4; ++rr) {
                int kk = r0 + rr * 16;
                *(float4*)&Bs[kk][k4*4] = *(const float4*)(B + (size_t)(kc + kk) * N + n0 + k4 * 4);
            }
        }
        __syncthreads();
        #pragma unroll 16
        for (int k = 0; k < 64; ++k) {
            float4 bv = *(float4*)&Bs[k][tx*4];
            #pragma unroll
            for (int i = 0; i < 4; ++i) {
                float a = As[ty*4+i][k];
                acc[i][0] += a * bv.x;
                acc[i][1] += a * bv.y;
                acc[i][2] += a * bv.z;
                acc[i][3] += a * bv.w;
            }
        }
        __syncthreads();
    }
    float4 bb = *(const float4*)(bias + n0 + tx*4);
    #pragma unroll
    for (int i = 0; i < 4; ++i) {
        float v0 = acc[i][0] + bb.x;
        float v1 = acc[i][1] + bb.y;
        float v2 = acc[i][2] + bb.z;
        float v3 = acc[i][3] + bb.w;
        if (dogelu) {
            v0 = 0.5f * v0 * (1.f + erff(v0 * 0.7071067811865475f));
            v1 = 0.5f * v1 * (1.f + erff(v1 * 0.7071067811865475f));
            v2 = 0.5f * v2 * (1.f + erff(v2 * 0.7071067811865475f));
            v3 = 0.5f * v3 * (1.f + erff(v3 * 0.7071067811865475f));
        }
        *(float4*)(C + (size_t)(m0 + ty*4 + i) * N + n0 + tx*4) = make_float4(v0, v1, v2, v3);
    }
}

// ---------------------------------------------------------------------------
// Causal attention, streaming softmax (no max pass: scores are O(1); masked
// entries skipped exactly, matching the -1e12 additive mask).
// grid = B*H*4 (quarter of query rows each); block = 256 threads.
// K/V rows [0, (q+1)*256) staged in smem as float4, read via broadcast.
// warp handles 32 query rows (one per lane); 8-u tiles.
// ---------------------------------------------------------------------------
__global__ void attn_kernel(const float* __restrict__ QKV, float* __restrict__ Att)
{
    extern __shared__ float4 sm4[];
    float4* kf = sm4;          // [1024*4]
    float4* vf = sm4 + 4096;   // [1024*4]
    const int quarter = blockIdx.x & 3;
    const int bh = blockIdx.x >> 2;
    const int b = bh >> 3, h = bh & 7;
    const int bT = b << 10;
    const int nrows = (quarter + 1) << 8;
    const int tid = threadIdx.x;

    for (int idx = tid; idx < nrows * 4; idx += 256) {
        int u = idx >> 2, c4 = idx & 3;
        const float* base = QKV + (size_t)(bT + u) * 384 + h * 16 + c4 * 4;
        kf[idx] = *(const float4*)(base + 128);
        vf[idx] = *(const float4*)(base + 256);
    }
    __syncthreads();

    const int w = tid >> 5, lane = tid & 31;
    const int t_base = (quarter << 8) + (w << 5);
    const int t = t_base + lane;

    const float* qp = QKV + (size_t)(bT + t) * 384 + h * 16;
    float4 q[4];
    q[0] = *(const float4*)(qp);
    q[1] = *(const float4*)(qp + 4);
    q[2] = *(const float4*)(qp + 8);
    q[3] = *(const float4*)(qp + 12);

    float4 a0 = make_float4(0,0,0,0), a1 = a0, a2 = a0, a3 = a0;
    float l = 0.f;

    for (int ub = 0; ub < t_base + 32; ub += 8) {
        float s[8] = {0,0,0,0,0,0,0,0};
        #pragma unroll
        for (int j4 = 0; j4 < 4; ++j4) {
            float4 qv = q[j4];
            #pragma unroll
            for (int uu = 0; uu < 8; ++uu) {
                float4 kk = kf[(ub + uu) * 4 + j4];
                s[uu] += qv.x*kk.x + qv.y*kk.y + qv.z*kk.z + qv.w*kk.w;
            }
        }
        #pragma unroll
        for (int uu = 0; uu < 8; ++uu) {
            int u = ub + uu;
            float p = (u <= t) ? __expf(s[uu] * 0.25f) : 0.f;
            l += p;
            float4 v0 = vf[u*4+0];
            a0.x += p*v0.x; a0.y += p*v0.y; a0.z += p*v0.z; a0.w += p*v0.w;
            float4 v1 = vf[u*4+1];
            a1.x += p*v1.x; a1.y += p*v1.y; a1.z += p*v1.z; a1.w += p*v1.w;
            float4 v2 = vf[u*4+2];
            a2.x += p*v2.x; a2.y += p*v2.y; a2.z += p*v2.z; a2.w += p*v2.w;
            float4 v3 = vf[u*4+3];
            a3.x += p*v3.x; a3.y += p*v3.y; a3.z += p*v3.z; a3.w += p*v3.w;
        }
    }
    float inv = 1.f / l;
    float* dst = Att + (size_t)(bT + t) * 128 + h * 16;
    ((float4*)dst)[0] = make_float4(a0.x*inv, a0.y*inv, a0.z*inv, a0.w*inv);
    ((float4*)dst)[1] = make_float4(a1.x*inv, a1.y*inv, a1.z*inv, a1.w*inv);
    ((float4*)dst)[2] = make_float4(a2.x*inv, a2.y*inv, a2.z*inv, a2.w*inv);
    ((float4*)dst)[3] = make_float4(a3.x*inv, a3.y*inv, a3.z*inv, a3.w*inv);
}

// ---------------------------------------------------------------------------
// proj + bias + residual + LayerNorm1 -> g_x1
// block handles 64 full rows (N=128); warp owns 8 rows -> in-block LN.
// dynamic smem: As 64x128 + Ws 128x128 = 96KB
// ---------------------------------------------------------------------------
__global__ void proj_ln_kernel(const float* __restrict__ A, const float* __restrict__ W,
                               const float* __restrict__ bias, const float* __restrict__ resid,
                               const float* __restrict__ gamma, const float* __restrict__ beta,
                               float* __restrict__ Out)
{
    extern __shared__ float sm[];
    float* As = sm;            // 64*128 (later reused for C tile)
    float* Ws = sm + 64 * 128; // 128*128
    const int m0 = blockIdx.x * 64;
    const int tid = threadIdx.x;
    const int w = tid >> 5, lane = tid & 31;
    {
        int k4 = tid & 31, r0 = tid >> 5;
        #pragma unroll
        for (int rr = 0; rr < 8; ++rr) {
            int r = r0 + rr * 8;
            *(float4*)&As[r * 128 + k4 * 4] = *(const float4*)(A + (size_t)(m0 + r) * 128 + k4 * 4);
        }
        #pragma unroll
        for (int ii = 0; ii < 16; ++ii) {
            int idx4 = tid + ii * 256;
            *(float4*)&Ws[idx4 * 4] = *(const float4*)(W + idx4 * 4);
        }
    }
    __syncthreads();
    float acc[8][4] = {};
    #pragma unroll 4
    for (int k = 0; k < 128; ++k) {
        float4 wv = *(float4*)&Ws[k * 128 + lane * 4];
        #pragma unroll
        for (int i = 0; i < 8; ++i) {
            float a = As[(w * 8 + i) * 128 + k];
            acc[i][0] += a * wv.x; acc[i][1] += a * wv.y;
            acc[i][2] += a * wv.z; acc[i][3] += a * wv.w;
        }
    }
    const int c = lane * 4;
    float4 bb = *(const float4*)(bias + c);
    // rows w*8+i are warp-private: safe to overwrite As without a barrier
    #pragma unroll
    for (int i = 0; i < 8; ++i) {
        int row = m0 + w * 8 + i;
        float4 rv = *(const float4*)(resid + (size_t)row * 128 + c);
        *(float4*)&As[(w * 8 + i) * 128 + c] =
            make_float4(acc[i][0]+bb.x+rv.x, acc[i][1]+bb.y+rv.y,
                        acc[i][2]+bb.z+rv.z, acc[i][3]+bb.w+rv.w);
    }
    float4 gg = *(const float4*)(gamma + c);
    float4 be = *(const float4*)(beta + c);
    #pragma unroll
    for (int i = 0; i < 8; ++i) {
        float4 v = *(float4*)&As[(w * 8 + i) * 128 + c];
        float s  = v.x + v.y + v.z + v.w;
        float sq = v.x*v.x + v.y*v.y + v.z*v.z + v.w*v.w;
        #pragma unroll
        for (int off = 16; off > 0; off >>= 1) {
            s  += __shfl_xor_sync(0xffffffffu, s,  off);
            sq += __shfl_xor_sync(0xffffffffu, sq, off);
        }
        float mean = s * (1.f/128.f);
        float var  = sq * (1.f/128.f) - mean * mean;
        float is   = rsqrtf(var + 1e-5f);
        int row = m0 + w * 8 + i;
        *(float4*)(Out + (size_t)row * 128 + c) =
            make_float4((v.x-mean)*is*gg.x+be.x, (v.y-mean)*is*gg.y+be.y,
                        (v.z-mean)*is*gg.z+be.z, (v.w-mean)*is*gg.w+be.w);
    }
}

// ---------------------------------------------------------------------------
// MLP2 (K=512) + bias + residual + LayerNorm2 -> d_out
// block handles 32 full rows; warp owns 4 rows.
// dynamic smem: As 32x128 + Ws 128x128 + Cs 32x128 = 96KB
// ---------------------------------------------------------------------------
__global__ void mlp2_ln_kernel(const float* __restrict__ A, const float* __restrict__ W,
                               const float* __restrict__ bias, const float* __restrict__ resid,
                               const float* __restrict__ gamma, const float* __restrict__ beta,
                               float* __restrict__ Out)
{
    extern __shared__ float sm[];
    float* As = sm;              // 32*128
    float* Ws = sm + 32 * 128;   // 128*128
    float* Cs = Ws + 128 * 128;  // 32*128
    const int m0 = blockIdx.x * 32;
    const int tid = threadIdx.x;
    const int w = tid >> 5, lane = tid & 31;
    float acc[4][4] = {};
    for (int kc = 0; kc < 512; kc += 128) {
        {
            int k4 = tid & 31, r0 = tid >> 5;
            #pragma unroll
            for (int rr = 0; rr < 4; ++rr) {
                int r = r0 + rr * 8;
                *(float4*)&As[r * 128 + k4 * 4] =
                    *(const float4*)(A + (size_t)(m0 + r) * 512 + kc + k4 * 4);
            }
            #pragma unroll
            for (int ii = 0; ii < 16; ++ii) {
                int idx4 = tid + ii * 256;
                *(float4*)&Ws[idx4 * 4] = *(const float4*)(W + (size_t)kc * 128 + idx4 * 4);
            }
        }
        __syncthreads();
        #pragma unroll 4
        for (int k = 0; k < 128; ++k) {
            float4 wv = *(float4*)&Ws[k * 128 + lane * 4];
            #pragma unroll
            for (int i = 0; i < 4; ++i) {
                float a = As[(w * 4 + i) * 128 + k];
                acc[i][0] += a * wv.x; acc[i][1] += a * wv.y;
                acc[i][2] += a * wv.z; acc[i][3] += a * wv.w;
            }
        }
        __syncthreads();
    }
    const int c = lane * 4;
    float4 bb = *(const float4*)(bias + c);
    #pragma unroll
    for (int i = 0; i < 4; ++i) {
        int row = m0 + w * 4 + i;
        float4 rv = *(const float4*)(resid + (size_t)row * 128 + c);
        *(float4*)&Cs[(w * 4 + i) * 128 + c] =
            make_float4(acc[i][0]+bb.x+rv.x, acc[i][1]+bb.y+rv.y,
                        acc[i][2]+bb.z+rv.z, acc[i][3]+bb.w+rv.w);
    }
    float4 gg = *(const float4*)(gamma + c);
    float4 be = *(const float4*)(beta + c);
    #pragma unroll
    for (int i = 0; i < 4; ++i) {
        float4 v = *(float4*)&Cs[(w * 4 + i) * 128 + c];
        float s  = v.x + v.y + v.z + v.w;
        float sq = v.x*v.x + v.y*v.y + v.z*v.z + v.w*v.w;
        #pragma unroll
        for (int off = 16; off > 0; off >>= 1) {
            s  += __shfl_xor_sync(0xffffffffu, s,  off);
            sq += __shfl_xor_sync(0xffffffffu, sq, off);
        }
        float mean = s * (1.f/128.f);
        float var  = sq * (1.f/128.f) - mean * mean;
        float is   = rsqrtf(var + 1e-5f);
        int row = m0 + w * 4 + i;
        *(float4*)(Out + (size_t)row * 128 + c) =
            make_float4((v.x-mean)*is*gg.x+be.x, (v.y-mean)*is*gg.y+be.y,
                        (v.z-mean)*is*gg.z+be.z, (v.w-mean)*is*gg.w+be.w);
    }
}

// ---------------------------------------------------------------------------
extern "C" void kernel_launch(void* const* d_in, const int* in_sizes, int n_in,
                              void* d_out, int out_size)
{
    const float* x   = (const float*)d_in[0];
    const float* Wq  = (const float*)d_in[1];
    const float* bq  = (const float*)d_in[2];
    const float* Wk  = (const float*)d_in[3];
    const float* bk  = (const float*)d_in[4];
    const float* Wv  = (const float*)d_in[5];
    const float* bv  = (const float*)d_in[6];
    const float* Wp  = (const float*)d_in[7];
    const float* bp  = (const float*)d_in[8];
    const float* W1  = (const float*)d_in[9];
    const float* b1  = (const float*)d_in[10];
    const float* W2  = (const float*)d_in[11];
    const float* b2  = (const float*)d_in[12];
    const float* g1  = (const float*)d_in[13];
    const float* be1 = (const float*)d_in[14];
    const float* g2  = (const float*)d_in[15];
    const float* be2 = (const float*)d_in[16];
    float* out = (float*)d_out;

    float *p_wqkv, *p_bqkv, *p_qkv, *p_att, *p_x1, *p_hid;
    cudaGetSymbolAddress((void**)&p_wqkv, g_wqkv);
    cudaGetSymbolAddress((void**)&p_bqkv, g_bqkv);
    cudaGetSymbolAddress((void**)&p_qkv,  g_qkv);
    cudaGetSymbolAddress((void**)&p_att,  g_att);
    cudaGetSymbolAddress((void**)&p_x1,   g_x1);
    cudaGetSymbolAddress((void**)&p_hid,  g_hid);

    cudaFuncSetAttribute(attn_kernel,    cudaFuncAttributeMaxDynamicSharedMemorySize, 131072);
    cudaFuncSetAttribute(proj_ln_kernel, cudaFuncAttributeMaxDynamicSharedMemorySize, 98304);
    cudaFuncSetAttribute(mlp2_ln_kernel, cudaFuncAttributeMaxDynamicSharedMemorySize, 98304);

    // 1. pack per-head QKV weights
    pack_w_kernel<<<(DMODEL * NQKV + 255) / 256, 256>>>(Wq, bq, Wk, bk, Wv, bv);
    // 2. QKV projection: [16384,128] @ [128,384]
    gemm_k128<<<dim3(BT_TOTAL / 64, NQKV / 64), 256>>>(x, p_wqkv, p_bqkv, p_qkv, NQKV, 0);
    // 3. causal attention
    attn_kernel<<<16 * 8 * 4, 256, 131072>>>(p_qkv, p_att);
    // 4. out-proj + residual + LN1
    proj_ln_kernel<<<BT_TOTAL / 64, 256, 98304>>>(p_att, Wp, bp, x, g1, be1, p_x1);
    // 5. MLP up + exact GELU: [16384,128] @ [128,512]
    gemm_k128<<<dim3(BT_TOTAL / 64, FFDIM / 64), 256>>>(p_x1, W1, b1, p_hid, FFDIM, 1);
    // 6. MLP down + residual + LN2 -> output
    mlp2_ln_kernel<<<BT_TOTAL / 32, 256, 98304>>>(p_hid, W2, b2, p_x1, g2, be2, out);
}